// round 12
// baseline (speedup 1.0000x reference)
#include <cuda_runtime.h>

#define NN 50000
#define INF 128
#define HCC 128   // H*OUT
#define ED 64
#define SORT_CTAS 296

typedef unsigned long long u64;

// ---------------- scratch (device globals; no allocs allowed) ----------------
__device__ float4 d_qg[NN * 64];   // per node: q(128) | g(128)
__device__ float4 d_kv[NN * 64];   // per node: k(128) | v(128)
__device__ float4 d_acc[NN * 64];  // per node: vacc(128) | tacc(128)
__device__ float  d_s[NN * 2];
__device__ int    d_cnt[NN];       // zero at load; re-zeroed every call in ksort scan
__device__ int    d_off[NN + 1];
__device__ int    d_pos[NN];
__device__ int2   d_sed[1600000];  // sorted-by-dst (src, edge_id)
__device__ unsigned d_gbar;        // grid barrier counter; reset by k1

// ---------------- packed fp32x2 helpers ----------------
__device__ __forceinline__ u64 bcast2(float v) {
    u64 r; asm("mov.b64 %0, {%1, %1};" : "=l"(r) : "f"(v)); return r;
}
__device__ __forceinline__ void fma2(u64& d, u64 a, u64 b) {
    asm("fma.rn.f32x2 %0, %1, %2, %0;" : "+l"(d) : "l"(a), "l"(b));
}
__device__ __forceinline__ float2 unpack2(u64 v) {
    float2 f; asm("mov.b64 {%0, %1}, %2;" : "=f"(f.x), "=f"(f.y) : "l"(v)); return f;
}

// grid barrier: atomic arrive, plain-load poll (no atomic-RMW serialization)
__device__ __forceinline__ void gbar_wait(unsigned target) {
    __syncthreads();
    if (threadIdx.x == 0) {
        __threadfence();
        atomicAdd(&d_gbar, 1u);
        while (*((volatile unsigned*)&d_gbar) < target) {}
        __threadfence();   // acquire: order subsequent reads after observed arrivals
    }
    __syncthreads();
}

// ---------------- KSORT: fused histogram + scan + scatter (1 launch) ----------------
__global__ __launch_bounds__(256) void ksort(const int* __restrict__ ei, int E) {
    const int t = threadIdx.x;
    const int gtid = blockIdx.x * 256 + t;
    const int gstride = SORT_CTAS * 256;

    // phase 1: histogram of dst
    for (int e = gtid; e < E; e += gstride)
        atomicAdd(&d_cnt[ei[E + e]], 1);

    gbar_wait((unsigned)SORT_CTAS);

    // phase 2: exclusive scan over d_cnt (block 0 only); re-zero d_cnt for next call
    if (blockIdx.x == 0) {
        __shared__ int ssum[256];
        const int per = (NN + 255) / 256;
        int base = t * per;
        int local = 0;
        for (int i = 0; i < per; i++) {
            int idx = base + i;
            if (idx < NN) local += d_cnt[idx];
        }
        ssum[t] = local;
        __syncthreads();
        for (int off = 1; off < 256; off <<= 1) {
            int v = (t >= off) ? ssum[t - off] : 0;
            __syncthreads();
            ssum[t] += v;
            __syncthreads();
        }
        int run = ssum[t] - local;   // exclusive prefix
        for (int i = 0; i < per; i++) {
            int idx = base + i;
            if (idx < NN) {
                int c = d_cnt[idx];
                d_off[idx] = run;
                d_pos[idx] = run;
                d_cnt[idx] = 0;      // restore invariant for next call
                run += c;
            }
        }
        if (t == 255) d_off[NN] = run;
        __threadfence();
    }

    gbar_wait(2u * (unsigned)SORT_CTAS);

    // phase 3: scatter (src, eid) into dst-sorted order
    for (int e = gtid; e < E; e += gstride) {
        int dst = ei[E + e];
        int pos = atomicAdd(&d_pos[dst], 1);
        d_sed[pos] = make_int2(ei[e], e);
    }
}

// ---------------- K1: C[N,512] = x[N,128] @ [Wq|Wk|Wv|Wskip] + bias ----------------
__global__ __launch_bounds__(256) void k1_gemm(
    const float* __restrict__ x,
    const float* __restrict__ Wq, const float* __restrict__ bq,
    const float* __restrict__ Wk, const float* __restrict__ bk,
    const float* __restrict__ Wv, const float* __restrict__ bv,
    const float* __restrict__ Wsk, const float* __restrict__ bsk,
    float* __restrict__ out, int n)
{
    // reset sort's grid barrier for the next kernel_launch call (stream-ordered: ksort done)
    if (blockIdx.x == 0 && blockIdx.y == 0 && threadIdx.x == 0) d_gbar = 0u;

    __shared__ float As[8][128];
    __shared__ float Bs[8][128];

    const int t = threadIdx.x;
    const int m0 = blockIdx.x * 128;
    const int which = blockIdx.y;

    const float* W;
    const float* bias;
    if (which == 0)      { W = Wq;  bias = bq;  }
    else if (which == 1) { W = Wk;  bias = bk;  }
    else if (which == 2) { W = Wv;  bias = bv;  }
    else                 { W = Wsk; bias = bsk; }

    const int ty = t >> 4;
    const int tx = t & 15;

    u64 acc2[4][8];
#pragma unroll
    for (int i = 0; i < 4; i++)
#pragma unroll
        for (int j = 0; j < 8; j++) acc2[i][j] = 0ULL;

    const int lrow = t >> 1;
    const int lcg  = t & 1;
    const int brow = t >> 5;
    const int bc   = (t & 31) * 4;

    for (int k0 = 0; k0 < 128; k0 += 8) {
        float4 av = make_float4(0.f, 0.f, 0.f, 0.f);
        int gr = m0 + lrow;
        if (gr < n) av = *(const float4*)(x + (long long)gr * 128 + k0 + lcg * 4);
        float4 bv4 = *(const float4*)(W + (k0 + brow) * 128 + bc);

        __syncthreads();
        As[lcg * 4 + 0][lrow] = av.x;
        As[lcg * 4 + 1][lrow] = av.y;
        As[lcg * 4 + 2][lrow] = av.z;
        As[lcg * 4 + 3][lrow] = av.w;
        *(float4*)&Bs[brow][bc] = bv4;
        __syncthreads();

#pragma unroll
        for (int kk = 0; kk < 8; kk++) {
            ulonglong2 a01 = *(const ulonglong2*)&As[kk][ty * 8];
            ulonglong2 a23 = *(const ulonglong2*)&As[kk][ty * 8 + 4];
            u64 ra2[4] = { a01.x, a01.y, a23.x, a23.y };

            float rb[8];
            *(float4*)(rb)     = *(float4*)&Bs[kk][tx * 8];
            *(float4*)(rb + 4) = *(float4*)&Bs[kk][tx * 8 + 4];
            u64 rbb[8];
#pragma unroll
            for (int j = 0; j < 8; j++) rbb[j] = bcast2(rb[j]);

#pragma unroll
            for (int i2 = 0; i2 < 4; i2++)
#pragma unroll
                for (int j = 0; j < 8; j++) fma2(acc2[i2][j], ra2[i2], rbb[j]);
        }
    }

    float bb[8];
#pragma unroll
    for (int j = 0; j < 8; j++) bb[j] = bias[tx * 8 + j];

    const int colf4 = tx * 2;
#pragma unroll
    for (int i2 = 0; i2 < 4; i2++) {
        float lo[8], hi[8];
#pragma unroll
        for (int j = 0; j < 8; j++) {
            float2 f = unpack2(acc2[i2][j]);
            lo[j] = f.x + bb[j];
            hi[j] = f.y + bb[j];
        }
#pragma unroll
        for (int half = 0; half < 2; half++) {
            int row = m0 + ty * 8 + 2 * i2 + half;
            if (row >= n) continue;
            const float* v = half ? hi : lo;
            float4 o0 = make_float4(v[0], v[1], v[2], v[3]);
            float4 o1 = make_float4(v[4], v[5], v[6], v[7]);
            long long r = row;
            if (which == 0) {
                d_qg[r * 64 + colf4] = o0; d_qg[r * 64 + colf4 + 1] = o1;
            } else if (which == 1) {
                d_kv[r * 64 + colf4] = o0; d_kv[r * 64 + colf4 + 1] = o1;
            } else if (which == 2) {
                d_kv[r * 64 + 32 + colf4] = o0; d_kv[r * 64 + 32 + colf4 + 1] = o1;
            } else {
                ((float4*)out)[r * 32 + colf4] = o0;
                ((float4*)out)[r * 32 + colf4 + 1] = o1;
            }
        }
    }
}

// ---------------- K1b: g[i,h,d] = sum_c We[d][h*64+c] * q[i,h,c] ----------------
__global__ __launch_bounds__(256) void k_g(const float* __restrict__ We, int n)
{
    __shared__ float WeT[128][64];
    __shared__ float4 qs[16][32];

    const int t = threadIdx.x;
    const int base = blockIdx.x * 16;

    for (int idx = t; idx < 64 * 128; idx += 256) {
        int d = idx >> 7, k = idx & 127;
        WeT[k][d] = We[idx];
    }
#pragma unroll
    for (int r = 0; r < 2; r++) {
        int idx4 = t + r * 256;
        int nl = idx4 >> 5, c4 = idx4 & 31;
        int node = base + nl;
        qs[nl][c4] = (node < n) ? d_qg[(long long)node * 64 + c4]
                                : make_float4(0.f, 0.f, 0.f, 0.f);
    }
    __syncthreads();

    const int nl = t >> 4;
    const int og = t & 15;
    const int h = og >> 3;
    const int d0 = (og * 8) & 63;
    const float* qrow = (const float*)&qs[nl][0];

    float a0[4] = {0.f, 0.f, 0.f, 0.f};
    float a1[4] = {0.f, 0.f, 0.f, 0.f};
#pragma unroll
    for (int c = 0; c < 64; c++) {
        float qv = qrow[h * 64 + c];
        float4 w0 = *(float4*)&WeT[h * 64 + c][d0];
        float4 w1 = *(float4*)&WeT[h * 64 + c][d0 + 4];
        a0[0] += qv * w0.x; a0[1] += qv * w0.y; a0[2] += qv * w0.z; a0[3] += qv * w0.w;
        a1[0] += qv * w1.x; a1[1] += qv * w1.y; a1[2] += qv * w1.z; a1[3] += qv * w1.w;
    }
    int node = base + nl;
    if (node < n) {
        long long r = node;
        d_qg[r * 64 + 32 + og * 2]     = make_float4(a0[0], a0[1], a0[2], a0[3]);
        d_qg[r * 64 + 32 + og * 2 + 1] = make_float4(a1[0], a1[1], a1[2], a1[3]);
    }
}

// ---------------- K2: one warp per node, depth-2 prefetch, ea streaming (__ldcs) ----------------
__global__ __launch_bounds__(256) void k2_nodes(const float* __restrict__ ea, int n)
{
    int node = (int)((blockIdx.x * 256u + threadIdx.x) >> 5);
    if (node >= n) return;
    const int lane = threadIdx.x & 31;
    const int li = lane & 15;
    const int h = lane >> 4;

    const int start = d_off[node];
    const int end   = d_off[node + 1];

    const float4* qg = d_qg + (long long)node * 64;
    float4 q4 = qg[lane];
    float4 g4 = qg[32 + lane];

    float4 vac = make_float4(0.f, 0.f, 0.f, 0.f);
    float4 tac = make_float4(0.f, 0.f, 0.f, 0.f);
    float sw = 0.f;

    for (int j0 = start; j0 < end; j0 += 32) {
        int nb = end - j0; if (nb > 32) nb = 32;
        int2 se = (lane < nb) ? d_sed[j0 + lane] : make_int2(0, 0);

        // prefetch edge 0
        int src = __shfl_sync(0xffffffffu, se.x, 0);
        int eid = __shfl_sync(0xffffffffu, se.y, 0);
        const float4* kvp = d_kv + (long long)src * 64;
        float4 kc = kvp[lane];
        float4 vc = kvp[32 + lane];
        float4 ec = __ldcs(((const float4*)ea) + (long long)eid * 16 + li);

        for (int jj = 0; jj < nb; jj++) {
            int jn = (jj + 1 < nb) ? (jj + 1) : jj;
            int srcn = __shfl_sync(0xffffffffu, se.x, jn);
            int eidn = __shfl_sync(0xffffffffu, se.y, jn);
            const float4* kvn = d_kv + (long long)srcn * 64;
            float4 kn = kvn[lane];
            float4 vn = kvn[32 + lane];
            float4 en = __ldcs(((const float4*)ea) + (long long)eidn * 16 + li);

            float p = q4.x * kc.x + q4.y * kc.y + q4.z * kc.z + q4.w * kc.w
                    + ec.x * g4.x + ec.y * g4.y + ec.z * g4.z + ec.w * g4.w;

            p += __shfl_xor_sync(0xffffffffu, p, 8);
            p += __shfl_xor_sync(0xffffffffu, p, 4);
            p += __shfl_xor_sync(0xffffffffu, p, 2);
            p += __shfl_xor_sync(0xffffffffu, p, 1);

            float w = __expf(p * 0.125f);   // 1/sqrt(64)
            sw += w;
            vac.x += w * vc.x; vac.y += w * vc.y; vac.z += w * vc.z; vac.w += w * vc.w;
            tac.x += w * ec.x; tac.y += w * ec.y; tac.z += w * ec.z; tac.w += w * ec.w;

            kc = kn; vc = vn; ec = en;
        }
    }

    float4* accp = d_acc + (long long)node * 64;
    accp[lane]      = vac;
    accp[32 + lane] = tac;
    if (li == 0) d_s[node * 2 + h] = sw;
}

// ---------------- K3: node epilogue ----------------
__global__ __launch_bounds__(512) void k3_epilogue(
    const float* __restrict__ We, float* __restrict__ out, int n)
{
    __shared__ float Wes[64][128];
    __shared__ float4 accs[16][64];

    const int t = threadIdx.x;
    const int base = blockIdx.x * 16;

    for (int idx = t; idx < 64 * 128; idx += 512) ((float*)Wes)[idx] = We[idx];
#pragma unroll
    for (int r = 0; r < 2; r++) {
        int idx4 = t + r * 512;
        int nl = idx4 >> 6, c4 = idx4 & 63;
        int node = base + nl;
        accs[nl][c4] = (node < n) ? d_acc[(long long)node * 64 + c4]
                                  : make_float4(0.f, 0.f, 0.f, 0.f);
    }
    __syncthreads();

    const int nl = t >> 5;
    const int c4i = t & 31;
    const int hc0 = c4i * 4;
    const int h = hc0 >> 6;
    const float* taccp = ((const float*)&accs[nl][32]);

    float ax = 0.f, ay = 0.f, az = 0.f, aw = 0.f;
#pragma unroll
    for (int d = 0; d < 64; d++) {
        float tv = taccp[h * 64 + d];
        float4 wv = *(float4*)&Wes[d][hc0];
        ax += tv * wv.x; ay += tv * wv.y; az += tv * wv.z; aw += tv * wv.w;
    }

    int node = base + nl;
    if (node >= n) return;
    float s = d_s[node * 2 + h];
    float inv = 1.f / (s + 1e-16f);
    float4 vac = accs[nl][c4i];
    float4 o = ((float4*)out)[(long long)node * 32 + c4i];
    o.x += (vac.x + ax) * inv;
    o.y += (vac.y + ay) * inv;
    o.z += (vac.z + az) * inv;
    o.w += (vac.w + aw) * inv;
    ((float4*)out)[(long long)node * 32 + c4i] = o;
}

// ---------------- launch ----------------
extern "C" void kernel_launch(void* const* d_in, const int* in_sizes, int n_in,
                              void* d_out, int out_size)
{
    const float* x   = (const float*)d_in[0];
    const int*   ei  = (const int*)d_in[1];     // int32 (JAX x64 disabled)
    const float* ea  = (const float*)d_in[2];
    const float* Wq  = (const float*)d_in[3];
    const float* bq  = (const float*)d_in[4];
    const float* Wk  = (const float*)d_in[5];
    const float* bk  = (const float*)d_in[6];
    const float* Wv  = (const float*)d_in[7];
    const float* bv  = (const float*)d_in[8];
    const float* We  = (const float*)d_in[9];
    const float* Wsk = (const float*)d_in[10];
    const float* bsk = (const float*)d_in[11];

    int n = in_sizes[0] / INF;        // 50000
    int E = in_sizes[2] / ED;         // 1600000
    float* out = (float*)d_out;

    ksort<<<SORT_CTAS, 256>>>(ei, E);                     // launch 1

    dim3 g1((n + 127) / 128, 4);
    k1_gemm<<<g1, 256>>>(x, Wq, bq, Wk, bk, Wv, bv, Wsk, bsk, out, n);  // launch 2

    k_g<<<(n + 15) / 16, 256>>>(We, n);                   // launch 3

    k2_nodes<<<(n * 32 + 255) / 256, 256>>>(ea, n);       // launch 4 (ncu slot)

    k3_epilogue<<<(n + 15) / 16, 512>>>(We, out, n);      // launch 5
}

// round 13
// speedup vs baseline: 1.0674x; 1.0674x over previous
#include <cuda_runtime.h>

#define NN 50000
#define INF 128
#define HCC 128   // H*OUT
#define ED 64

typedef unsigned long long u64;

// ---------------- scratch (device globals; no allocs allowed) ----------------
__device__ float4 d_qg[NN * 64];   // per node: q(128) | g(128)
__device__ float4 d_kv[NN * 64];   // per node: k(128) | v(128)
__device__ float4 d_acc[NN * 64];  // per node: vacc(128) | tacc(128)
__device__ float  d_s[NN * 2];
__device__ int    d_cnt[NN];
__device__ int    d_off[NN + 1];
__device__ int    d_pos[NN];
__device__ int2   d_sed[1600000];  // sorted-by-dst (src, edge_id)

// ---------------- packed fp32x2 helpers ----------------
__device__ __forceinline__ u64 bcast2(float v) {
    u64 r; asm("mov.b64 %0, {%1, %1};" : "=l"(r) : "f"(v)); return r;
}
__device__ __forceinline__ void fma2(u64& d, u64 a, u64 b) {
    asm("fma.rn.f32x2 %0, %1, %2, %0;" : "+l"(d) : "l"(a), "l"(b));
}
__device__ __forceinline__ float2 unpack2(u64 v) {
    float2 f; asm("mov.b64 {%0, %1}, %2;" : "=f"(f.x), "=f"(f.y) : "l"(v)); return f;
}

// ---------------- K0: zero histogram ----------------
__global__ void k0_zero() {
    int i = blockIdx.x * blockDim.x + threadIdx.x;
    if (i < NN) d_cnt[i] = 0;
}

// ---------------- sort pass 1: histogram of dst ----------------
__global__ void khist(const int* __restrict__ ei, int E) {
    int stride = gridDim.x * blockDim.x;
    for (int e = blockIdx.x * blockDim.x + threadIdx.x; e < E; e += stride)
        atomicAdd(&d_cnt[ei[E + e]], 1);
}

// ---------------- sort pass 2: exclusive scan (single CTA) ----------------
__global__ __launch_bounds__(1024) void kscan() {
    __shared__ int ssum[1024];
    const int T = 1024, per = (NN + T - 1) / T;
    int t = threadIdx.x;
    int base = t * per;
    int local = 0;
    for (int i = 0; i < per; i++) {
        int idx = base + i;
        if (idx < NN) local += d_cnt[idx];
    }
    ssum[t] = local;
    __syncthreads();
    for (int off = 1; off < T; off <<= 1) {
        int v = (t >= off) ? ssum[t - off] : 0;
        __syncthreads();
        ssum[t] += v;
        __syncthreads();
    }
    int run = ssum[t] - local;   // exclusive prefix
    for (int i = 0; i < per; i++) {
        int idx = base + i;
        if (idx < NN) {
            int c = d_cnt[idx];
            d_off[idx] = run;
            d_pos[idx] = run;
            run += c;
        }
    }
    if (t == T - 1) d_off[NN] = run;
}

// ---------------- sort pass 3: scatter (src, eid) into dst-sorted order ----------------
__global__ void kscatter(const int* __restrict__ ei, int E) {
    int stride = gridDim.x * blockDim.x;
    for (int e = blockIdx.x * blockDim.x + threadIdx.x; e < E; e += stride) {
        int dst = ei[E + e];
        int pos = atomicAdd(&d_pos[dst], 1);
        d_sed[pos] = make_int2(ei[e], e);
    }
}

// ---------------- K1: C[N,512] = x[N,128] @ [Wq|Wk|Wv|Wskip] + bias ----------------
__global__ __launch_bounds__(256) void k1_gemm(
    const float* __restrict__ x,
    const float* __restrict__ Wq, const float* __restrict__ bq,
    const float* __restrict__ Wk, const float* __restrict__ bk,
    const float* __restrict__ Wv, const float* __restrict__ bv,
    const float* __restrict__ Wsk, const float* __restrict__ bsk,
    float* __restrict__ out, int n)
{
    __shared__ float As[8][128];
    __shared__ float Bs[8][128];

    const int t = threadIdx.x;
    const int m0 = blockIdx.x * 128;
    const int which = blockIdx.y;

    const float* W;
    const float* bias;
    if (which == 0)      { W = Wq;  bias = bq;  }
    else if (which == 1) { W = Wk;  bias = bk;  }
    else if (which == 2) { W = Wv;  bias = bv;  }
    else                 { W = Wsk; bias = bsk; }

    const int ty = t >> 4;
    const int tx = t & 15;

    u64 acc2[4][8];
#pragma unroll
    for (int i = 0; i < 4; i++)
#pragma unroll
        for (int j = 0; j < 8; j++) acc2[i][j] = 0ULL;

    const int lrow = t >> 1;
    const int lcg  = t & 1;
    const int brow = t >> 5;
    const int bc   = (t & 31) * 4;

    for (int k0 = 0; k0 < 128; k0 += 8) {
        float4 av = make_float4(0.f, 0.f, 0.f, 0.f);
        int gr = m0 + lrow;
        if (gr < n) av = *(const float4*)(x + (long long)gr * 128 + k0 + lcg * 4);
        float4 bv4 = *(const float4*)(W + (k0 + brow) * 128 + bc);

        __syncthreads();
        As[lcg * 4 + 0][lrow] = av.x;
        As[lcg * 4 + 1][lrow] = av.y;
        As[lcg * 4 + 2][lrow] = av.z;
        As[lcg * 4 + 3][lrow] = av.w;
        *(float4*)&Bs[brow][bc] = bv4;
        __syncthreads();

#pragma unroll
        for (int kk = 0; kk < 8; kk++) {
            ulonglong2 a01 = *(const ulonglong2*)&As[kk][ty * 8];
            ulonglong2 a23 = *(const ulonglong2*)&As[kk][ty * 8 + 4];
            u64 ra2[4] = { a01.x, a01.y, a23.x, a23.y };

            float rb[8];
            *(float4*)(rb)     = *(float4*)&Bs[kk][tx * 8];
            *(float4*)(rb + 4) = *(float4*)&Bs[kk][tx * 8 + 4];
            u64 rbb[8];
#pragma unroll
            for (int j = 0; j < 8; j++) rbb[j] = bcast2(rb[j]);

#pragma unroll
            for (int i2 = 0; i2 < 4; i2++)
#pragma unroll
                for (int j = 0; j < 8; j++) fma2(acc2[i2][j], ra2[i2], rbb[j]);
        }
    }

    float bb[8];
#pragma unroll
    for (int j = 0; j < 8; j++) bb[j] = bias[tx * 8 + j];

    const int colf4 = tx * 2;
#pragma unroll
    for (int i2 = 0; i2 < 4; i2++) {
        float lo[8], hi[8];
#pragma unroll
        for (int j = 0; j < 8; j++) {
            float2 f = unpack2(acc2[i2][j]);
            lo[j] = f.x + bb[j];
            hi[j] = f.y + bb[j];
        }
#pragma unroll
        for (int half = 0; half < 2; half++) {
            int row = m0 + ty * 8 + 2 * i2 + half;
            if (row >= n) continue;
            const float* v = half ? hi : lo;
            float4 o0 = make_float4(v[0], v[1], v[2], v[3]);
            float4 o1 = make_float4(v[4], v[5], v[6], v[7]);
            long long r = row;
            if (which == 0) {
                d_qg[r * 64 + colf4] = o0; d_qg[r * 64 + colf4 + 1] = o1;
            } else if (which == 1) {
                d_kv[r * 64 + colf4] = o0; d_kv[r * 64 + colf4 + 1] = o1;
            } else if (which == 2) {
                d_kv[r * 64 + 32 + colf4] = o0; d_kv[r * 64 + 32 + colf4 + 1] = o1;
            } else {
                ((float4*)out)[r * 32 + colf4] = o0;
                ((float4*)out)[r * 32 + colf4 + 1] = o1;
            }
        }
    }
}

// ---------------- K1b: g[i,h,d] = sum_c We[d][h*64+c] * q[i,h,c] ----------------
__global__ __launch_bounds__(256) void k_g(const float* __restrict__ We, int n)
{
    __shared__ float WeT[128][64];
    __shared__ float4 qs[16][32];

    const int t = threadIdx.x;
    const int base = blockIdx.x * 16;

    for (int idx = t; idx < 64 * 128; idx += 256) {
        int d = idx >> 7, k = idx & 127;
        WeT[k][d] = We[idx];
    }
#pragma unroll
    for (int r = 0; r < 2; r++) {
        int idx4 = t + r * 256;
        int nl = idx4 >> 5, c4 = idx4 & 31;
        int node = base + nl;
        qs[nl][c4] = (node < n) ? d_qg[(long long)node * 64 + c4]
                                : make_float4(0.f, 0.f, 0.f, 0.f);
    }
    __syncthreads();

    const int nl = t >> 4;
    const int og = t & 15;
    const int h = og >> 3;
    const int d0 = (og * 8) & 63;
    const float* qrow = (const float*)&qs[nl][0];

    float a0[4] = {0.f, 0.f, 0.f, 0.f};
    float a1[4] = {0.f, 0.f, 0.f, 0.f};
#pragma unroll
    for (int c = 0; c < 64; c++) {
        float qv = qrow[h * 64 + c];
        float4 w0 = *(float4*)&WeT[h * 64 + c][d0];
        float4 w1 = *(float4*)&WeT[h * 64 + c][d0 + 4];
        a0[0] += qv * w0.x; a0[1] += qv * w0.y; a0[2] += qv * w0.z; a0[3] += qv * w0.w;
        a1[0] += qv * w1.x; a1[1] += qv * w1.y; a1[2] += qv * w1.z; a1[3] += qv * w1.w;
    }
    int node = base + nl;
    if (node < n) {
        long long r = node;
        d_qg[r * 64 + 32 + og * 2]     = make_float4(a0[0], a0[1], a0[2], a0[3]);
        d_qg[r * 64 + 32 + og * 2 + 1] = make_float4(a1[0], a1[1], a1[2], a1[3]);
    }
}

// ---------------- K2: one warp per node, depth-2 prefetch, ea streaming (__ldcs) ----------------
__global__ __launch_bounds__(256) void k2_nodes(const float* __restrict__ ea, int n)
{
    int node = (int)((blockIdx.x * 256u + threadIdx.x) >> 5);
    if (node >= n) return;
    const int lane = threadIdx.x & 31;
    const int li = lane & 15;
    const int h = lane >> 4;

    const int start = d_off[node];
    const int end   = d_off[node + 1];

    const float4* qg = d_qg + (long long)node * 64;
    float4 q4 = qg[lane];
    float4 g4 = qg[32 + lane];

    float4 vac = make_float4(0.f, 0.f, 0.f, 0.f);
    float4 tac = make_float4(0.f, 0.f, 0.f, 0.f);
    float sw = 0.f;

    for (int j0 = start; j0 < end; j0 += 32) {
        int nb = end - j0; if (nb > 32) nb = 32;
        int2 se = (lane < nb) ? d_sed[j0 + lane] : make_int2(0, 0);

        // prefetch edge 0
        int src = __shfl_sync(0xffffffffu, se.x, 0);
        int eid = __shfl_sync(0xffffffffu, se.y, 0);
        const float4* kvp = d_kv + (long long)src * 64;
        float4 kc = kvp[lane];
        float4 vc = kvp[32 + lane];
        float4 ec = __ldcs(((const float4*)ea) + (long long)eid * 16 + li);

        for (int jj = 0; jj < nb; jj++) {
            int jn = (jj + 1 < nb) ? (jj + 1) : jj;
            int srcn = __shfl_sync(0xffffffffu, se.x, jn);
            int eidn = __shfl_sync(0xffffffffu, se.y, jn);
            const float4* kvn = d_kv + (long long)srcn * 64;
            float4 kn = kvn[lane];
            float4 vn = kvn[32 + lane];
            float4 en = __ldcs(((const float4*)ea) + (long long)eidn * 16 + li);

            float p = q4.x * kc.x + q4.y * kc.y + q4.z * kc.z + q4.w * kc.w
                    + ec.x * g4.x + ec.y * g4.y + ec.z * g4.z + ec.w * g4.w;

            p += __shfl_xor_sync(0xffffffffu, p, 8);
            p += __shfl_xor_sync(0xffffffffu, p, 4);
            p += __shfl_xor_sync(0xffffffffu, p, 2);
            p += __shfl_xor_sync(0xffffffffu, p, 1);

            float w = __expf(p * 0.125f);   // 1/sqrt(64)
            sw += w;
            vac.x += w * vc.x; vac.y += w * vc.y; vac.z += w * vc.z; vac.w += w * vc.w;
            tac.x += w * ec.x; tac.y += w * ec.y; tac.z += w * ec.z; tac.w += w * ec.w;

            kc = kn; vc = vn; ec = en;
        }
    }

    float4* accp = d_acc + (long long)node * 64;
    accp[lane]      = vac;
    accp[32 + lane] = tac;
    if (li == 0) d_s[node * 2 + h] = sw;
}

// ---------------- K3: node epilogue ----------------
__global__ __launch_bounds__(512) void k3_epilogue(
    const float* __restrict__ We, float* __restrict__ out, int n)
{
    __shared__ float Wes[64][128];
    __shared__ float4 accs[16][64];

    const int t = threadIdx.x;
    const int base = blockIdx.x * 16;

    for (int idx = t; idx < 64 * 128; idx += 512) ((float*)Wes)[idx] = We[idx];
#pragma unroll
    for (int r = 0; r < 2; r++) {
        int idx4 = t + r * 512;
        int nl = idx4 >> 6, c4 = idx4 & 63;
        int node = base + nl;
        accs[nl][c4] = (node < n) ? d_acc[(long long)node * 64 + c4]
                                  : make_float4(0.f, 0.f, 0.f, 0.f);
    }
    __syncthreads();

    const int nl = t >> 5;
    const int c4i = t & 31;
    const int hc0 = c4i * 4;
    const int h = hc0 >> 6;
    const float* taccp = ((const float*)&accs[nl][32]);

    float ax = 0.f, ay = 0.f, az = 0.f, aw = 0.f;
#pragma unroll
    for (int d = 0; d < 64; d++) {
        float tv = taccp[h * 64 + d];
        float4 wv = *(float4*)&Wes[d][hc0];
        ax += tv * wv.x; ay += tv * wv.y; az += tv * wv.z; aw += tv * wv.w;
    }

    int node = base + nl;
    if (node >= n) return;
    float s = d_s[node * 2 + h];
    float inv = 1.f / (s + 1e-16f);
    float4 vac = accs[nl][c4i];
    float4 o = ((float4*)out)[(long long)node * 32 + c4i];
    o.x += (vac.x + ax) * inv;
    o.y += (vac.y + ay) * inv;
    o.z += (vac.z + az) * inv;
    o.w += (vac.w + aw) * inv;
    ((float4*)out)[(long long)node * 32 + c4i] = o;
}

// ---------------- launch ----------------
extern "C" void kernel_launch(void* const* d_in, const int* in_sizes, int n_in,
                              void* d_out, int out_size)
{
    const float* x   = (const float*)d_in[0];
    const int*   ei  = (const int*)d_in[1];     // int32 (JAX x64 disabled)
    const float* ea  = (const float*)d_in[2];
    const float* Wq  = (const float*)d_in[3];
    const float* bq  = (const float*)d_in[4];
    const float* Wk  = (const float*)d_in[5];
    const float* bk  = (const float*)d_in[6];
    const float* Wv  = (const float*)d_in[7];
    const float* bv  = (const float*)d_in[8];
    const float* We  = (const float*)d_in[9];
    const float* Wsk = (const float*)d_in[10];
    const float* bsk = (const float*)d_in[11];

    int n = in_sizes[0] / INF;        // 50000
    int E = in_sizes[2] / ED;         // 1600000
    float* out = (float*)d_out;

    // sort passes 1-2 first; k1 (independent of sort) takes ncu slot 4
    k0_zero<<<(NN + 255) / 256, 256>>>();                 // launch 1
    khist<<<1184, 256>>>(ei, E);                          // launch 2
    kscan<<<1, 1024>>>();                                 // launch 3

    dim3 g1((n + 127) / 128, 4);
    k1_gemm<<<g1, 256>>>(x, Wq, bq, Wk, bk, Wv, bv, Wsk, bsk, out, n);  // launch 4 (ncu slot)

    kscatter<<<1184, 256>>>(ei, E);                       // launch 5
    k_g<<<(n + 15) / 16, 256>>>(We, n);                   // launch 6
    k2_nodes<<<(n * 32 + 255) / 256, 256>>>(ea, n);       // launch 7
    k3_epilogue<<<(n + 15) / 16, 512>>>(We, out, n);      // launch 8
}